// round 8
// baseline (speedup 1.0000x reference)
#include <cuda_runtime.h>
#include <cuda_bf16.h>
#include <cstdint>

#define N_NODES 50000
#define K_NBR 16
#define D 256
#define LN_EPS 1e-5f
#define MR 64
#define NB ((N_NODES + MR - 1) / MR)   // 782

// ---------------------------------------------------------------------------
// Device-global scratch (allocation-free rule): transposed bf16 hi/lo weights
// ---------------------------------------------------------------------------
__device__ __align__(16) __nv_bfloat16 g_wthi[D * D];   // W^T hi [n][k]
__device__ __align__(16) __nv_bfloat16 g_wtlo[D * D];   // W^T lo [n][k]

// ---------------------------------------------------------------------------
// PTX helpers (baseline sm_80+ — must compile at virtual compute_103)
// ---------------------------------------------------------------------------
__device__ __forceinline__ uint32_t smem_to_u32(const void* p) {
    uint32_t a;
    asm("{ .reg .u64 t; cvta.to.shared.u64 t, %1; cvt.u32.u64 %0, t; }"
        : "=r"(a) : "l"(p));
    return a;
}

#define CP_ASYNC16(dst, src, szz) \
    asm volatile("cp.async.cg.shared.global [%0], [%1], 16, %2;" \
                 :: "r"(dst), "l"(src), "r"(szz) : "memory")
#define CP_COMMIT() asm volatile("cp.async.commit_group;" ::: "memory")
#define CP_WAIT(n)  asm volatile("cp.async.wait_group %0;" :: "n"(n) : "memory")

#define LDSM_X4(d, addr) \
    asm volatile("ldmatrix.sync.aligned.m8n8.x4.shared.b16 {%0,%1,%2,%3}, [%4];" \
                 : "=r"((d)[0]), "=r"((d)[1]), "=r"((d)[2]), "=r"((d)[3]) \
                 : "r"(addr))

__device__ __forceinline__ void mma16816(float c[4], const uint32_t a[4],
                                         uint32_t b0, uint32_t b1) {
    asm volatile(
        "mma.sync.aligned.m16n8k16.row.col.f32.bf16.bf16.f32 "
        "{%0,%1,%2,%3}, {%4,%5,%6,%7}, {%8,%9}, {%0,%1,%2,%3};"
        : "+f"(c[0]), "+f"(c[1]), "+f"(c[2]), "+f"(c[3])
        : "r"(a[0]), "r"(a[1]), "r"(a[2]), "r"(a[3]), "r"(b0), "r"(b1));
}

// ---------------------------------------------------------------------------
// SMEM layout (94 KB -> 2 CTAs/SM)
//   A_HI/LO : 64 rows x 128 B (current K-chunk tile, swizzled)  8 KB each
//   B_HI/LO : 256 n-rows x 128 B (current K-chunk, swizzled)    32 KB each
// ---------------------------------------------------------------------------
#define OFF_A_HI   0
#define OFF_A_LO   8192
#define OFF_B_HI   16384
#define OFF_B_LO   49152
#define OFF_SNB    81920    // int  snb[64][16]  = 4 KB
#define OFF_SW     86016    // float sw[64][16]  = 4 KB (normalized in place)
#define OFF_BIAS   90112
#define OFF_GAMMA  91136
#define OFF_BETA   92160
#define OFF_RED    93184    // float2 red[64][4] = 2 KB
#define OFF_STAT   95232    // float2 stat[64]
#define SMEM_TOTAL 95744

// ---------------------------------------------------------------------------
// Kernel 0: W [D_in, D_out] -> W^T bf16 hi/lo via coalesced smem transpose
// ---------------------------------------------------------------------------
__global__ __launch_bounds__(256) void prep_w(const float* __restrict__ W) {
    __shared__ float tile[32][33];
    const int bx = blockIdx.x * 32;   // n tile
    const int by = blockIdx.y * 32;   // k tile
    const int tx = threadIdx.x;
    const int ty = threadIdx.y;

#pragma unroll
    for (int i = 0; i < 4; i++) {
        const int k = by + ty + i * 8;
        tile[ty + i * 8][tx] = W[k * D + bx + tx];
    }
    __syncthreads();
#pragma unroll
    for (int i = 0; i < 4; i++) {
        const int n = bx + ty + i * 8;
        const int k = by + tx;
        const float v = tile[tx][ty + i * 8];
        const __nv_bfloat16 hi = __float2bfloat16(v);
        const __nv_bfloat16 lo = __float2bfloat16(v - __bfloat162float(hi));
        g_wthi[n * D + k] = hi;
        g_wtlo[n * D + k] = lo;
    }
}

// ---------------------------------------------------------------------------
// Fused kernel: per-chunk weighted gather -> smem bf16 hi/lo -> mma.sync
// 3-term GEMM -> fused LayerNorm. 256 threads = 8 warps (2 row x 4 col),
// warp tile 32m x 64n, CTA tile 64 rows x 256 cols, K chunked x64.
// ---------------------------------------------------------------------------
__global__ __launch_bounds__(256, 2) void fused_gather_gemm_ln(
    const float* __restrict__ features,
    const int* __restrict__ neighbors,
    const float* __restrict__ weights,
    const float* __restrict__ bias,
    const float* __restrict__ gamma,
    const float* __restrict__ beta,
    float* __restrict__ out)
{
    extern __shared__ char smem[];
    const uint32_t su = smem_to_u32(smem);
    const int tid  = threadIdx.x;
    const int warp = tid >> 5;
    const int lid  = tid & 31;
    const int wr   = warp >> 2;   // 0..1 : rows wr*32..+31
    const int wc   = warp & 3;    // 0..3 : cols wc*64..+63
    const int grp  = lid >> 3;
    const int idx  = lid & 7;
    const int rb   = blockIdx.x * MR;

    // ---- params + per-node tables ----
    if (tid < D) {
        ((float*)(smem + OFF_BIAS))[tid]  = bias[tid];
        ((float*)(smem + OFF_GAMMA))[tid] = gamma[tid];
        ((float*)(smem + OFF_BETA))[tid]  = beta[tid];
    }
    float* swp = (float*)(smem + OFF_SW);
    int*   snp = (int*)(smem + OFF_SNB);
    for (int i = tid; i < MR * K_NBR; i += 256) {
        const int nl = i >> 4, kk = i & 15;
        const int gn = rb + nl;
        float w = 0.f; int nb = 0;
        if (gn < N_NODES) {
            w  = weights[gn * K_NBR + kk];
            nb = neighbors[gn * K_NBR + kk];   // int32 (JAX x64-off downcast)
        }
        swp[i] = w; snp[i] = nb;
    }
    __syncthreads();
    // normalize weights in place (zero-sum fallback = uniform)
    if (tid < MR) {
        float ws = 0.f;
#pragma unroll
        for (int k = 0; k < K_NBR; k++) ws += swp[tid * K_NBR + k];
        const bool z = (ws == 0.f);
        const float inv = z ? 0.f : 1.f / ws;
#pragma unroll
        for (int k = 0; k < K_NBR; k++)
            swp[tid * K_NBR + k] = z ? (1.f / (float)K_NBR)
                                     : swp[tid * K_NBR + k] * inv;
    }

    float acc[2][8][4];
#pragma unroll
    for (int mt = 0; mt < 2; mt++)
#pragma unroll
        for (int nt = 0; nt < 8; nt++)
#pragma unroll
            for (int q = 0; q < 4; q++) acc[mt][nt][q] = 0.f;

    // ldmatrix lane bases (row stride 128 B, chunk-local tiles)
    const int a_kh = grp >> 1;
    uint32_t a_base[2];
#pragma unroll
    for (int mt = 0; mt < 2; mt++)
        a_base[mt] = (uint32_t)((wr * 32 + mt * 16 + (grp & 1) * 8 + idx) * 128);
    const int b_kh = grp & 1;
    uint32_t b_base[4];
#pragma unroll
    for (int p = 0; p < 4; p++)
        b_base[p] = (uint32_t)((wc * 64 + p * 16 + (grp >> 1) * 8 + idx) * 128);
    const uint32_t xorv = (uint32_t)(idx * 16);

    const float2* __restrict__ f2 = (const float2*)features;

    __syncthreads();

    // ================= mainloop over 4 K-chunks of 64 =================
    for (int c = 0; c < 4; c++) {
        // ---- stage B chunk c via cp.async (hidden behind the gather) ----
#pragma unroll
        for (int i = 0; i < 8; i++) {
            const int e = i * 256 + tid;
            const int n = e >> 3, u = e & 7;
            const uint32_t dst =
                su + ((uint32_t)(n * 128 + u * 16) ^ (uint32_t)((n & 7) * 16));
            const size_t go = (size_t)n * D + c * 64 + u * 8;
            CP_ASYNC16(dst + OFF_B_HI, (const char*)&g_wthi[go], 16);
            CP_ASYNC16(dst + OFF_B_LO, (const char*)&g_wtlo[go], 16);
        }
        CP_COMMIT();

        // ---- gather chunk c: each warp handles 8 nodes, lane owns 2 cols ----
        for (int it = 0; it < 8; it++) {
            const int nl = it * 8 + warp;
            const float* wv = swp + nl * K_NBR;
            const int*   nv = snp + nl * K_NBR;
            float a0 = 0.f, a1 = 0.f;
#pragma unroll
            for (int k = 0; k < K_NBR; k++) {
                const float w = wv[k];
                const float2 v = f2[(size_t)nv[k] * (D / 2) + c * 32 + lid];
                a0 += w * v.x;
                a1 += w * v.y;
            }
            const __nv_bfloat16 h0 = __float2bfloat16(a0);
            const __nv_bfloat16 h1 = __float2bfloat16(a1);
            const __nv_bfloat16 l0 = __float2bfloat16(a0 - __bfloat162float(h0));
            const __nv_bfloat16 l1 = __float2bfloat16(a1 - __bfloat162float(h1));
            const uint32_t hp = (uint32_t)__bfloat16_as_ushort(h0)
                              | ((uint32_t)__bfloat16_as_ushort(h1) << 16);
            const uint32_t lp = (uint32_t)__bfloat16_as_ushort(l0)
                              | ((uint32_t)__bfloat16_as_ushort(l1) << 16);
            const uint32_t ad = (uint32_t)(nl * 128)
                              + (((uint32_t)(lid * 4)) ^ ((uint32_t)((nl & 7) * 16)));
            *(uint32_t*)(smem + OFF_A_HI + ad) = hp;
            *(uint32_t*)(smem + OFF_A_LO + ad) = lp;
        }

        CP_WAIT(0);
        __syncthreads();   // A writes + B arrival visible to all warps

        // ---- mma chunk c (3-term bf16 split) ----
#pragma unroll
        for (int ks = 0; ks < 4; ks++) {
            const uint32_t xa = ((uint32_t)(ks * 32 + a_kh * 16)) ^ xorv;
            const uint32_t xb = ((uint32_t)(ks * 32 + b_kh * 16)) ^ xorv;

            uint32_t ah[2][4], al[2][4];
#pragma unroll
            for (int mt = 0; mt < 2; mt++) {
                const uint32_t aaddr = su + OFF_A_HI + a_base[mt] + xa;
                LDSM_X4(ah[mt], aaddr);
                LDSM_X4(al[mt], aaddr + (OFF_A_LO - OFF_A_HI));
            }
#pragma unroll
            for (int p = 0; p < 4; p++) {
                uint32_t bh[4], bl[4];
                const uint32_t baddr = su + OFF_B_HI + b_base[p] + xb;
                LDSM_X4(bh, baddr);
                LDSM_X4(bl, baddr + (OFF_B_LO - OFF_B_HI));
#pragma unroll
                for (int h = 0; h < 2; h++) {
                    const int nt = p * 2 + h;
                    const uint32_t b0h = bh[h * 2], b1h = bh[h * 2 + 1];
                    const uint32_t b0l = bl[h * 2], b1l = bl[h * 2 + 1];
#pragma unroll
                    for (int mt = 0; mt < 2; mt++) {
                        mma16816(acc[mt][nt], ah[mt], b0h, b1h);
                        mma16816(acc[mt][nt], al[mt], b0h, b1h);
                        mma16816(acc[mt][nt], ah[mt], b0l, b1l);
                    }
                }
            }
        }
        __syncthreads();   // A/B buffers free for next chunk
    }

    // ================= epilogue: bias + LayerNorm + affine =================
    const float* bias_s  = (const float*)(smem + OFF_BIAS);
    const float* gamma_s = (const float*)(smem + OFF_GAMMA);
    const float* beta_s  = (const float*)(smem + OFF_BETA);
    float2* red  = (float2*)(smem + OFF_RED);    // red[row*4 + wc]
    float2* stat = (float2*)(smem + OFF_STAT);   // (mean, rstd)

#pragma unroll
    for (int mt = 0; mt < 2; mt++)
#pragma unroll
        for (int nt = 0; nt < 8; nt++) {
            const int col = wc * 64 + nt * 8 + (lid & 3) * 2;
            acc[mt][nt][0] += bias_s[col];
            acc[mt][nt][1] += bias_s[col + 1];
            acc[mt][nt][2] += bias_s[col];
            acc[mt][nt][3] += bias_s[col + 1];
        }

    float s1[4], s2[4];
#pragma unroll
    for (int mt = 0; mt < 2; mt++) {
        float a1 = 0.f, a2 = 0.f, b1 = 0.f, b2 = 0.f;
#pragma unroll
        for (int nt = 0; nt < 8; nt++) {
            a1 += acc[mt][nt][0] + acc[mt][nt][1];
            a2 += acc[mt][nt][0] * acc[mt][nt][0] + acc[mt][nt][1] * acc[mt][nt][1];
            b1 += acc[mt][nt][2] + acc[mt][nt][3];
            b2 += acc[mt][nt][2] * acc[mt][nt][2] + acc[mt][nt][3] * acc[mt][nt][3];
        }
        s1[mt * 2] = a1;     s2[mt * 2] = a2;
        s1[mt * 2 + 1] = b1; s2[mt * 2 + 1] = b2;
    }
#pragma unroll
    for (int z = 1; z <= 2; z <<= 1)
#pragma unroll
        for (int i = 0; i < 4; i++) {
            s1[i] += __shfl_xor_sync(0xffffffffu, s1[i], z);
            s2[i] += __shfl_xor_sync(0xffffffffu, s2[i], z);
        }

    if ((lid & 3) == 0) {
        const int g = lid >> 2;
#pragma unroll
        for (int mt = 0; mt < 2; mt++)
#pragma unroll
            for (int h = 0; h < 2; h++) {
                const int row = wr * 32 + mt * 16 + h * 8 + g;
                red[row * 4 + wc] = make_float2(s1[mt * 2 + h], s2[mt * 2 + h]);
            }
    }
    __syncthreads();

    if (tid < MR) {
        float t1 = 0.f, t2 = 0.f;
#pragma unroll
        for (int w = 0; w < 4; w++) {
            const float2 v = red[tid * 4 + w];
            t1 += v.x; t2 += v.y;
        }
        const float mean = t1 * (1.f / (float)D);
        const float var  = t2 * (1.f / (float)D) - mean * mean;
        stat[tid] = make_float2(mean, rsqrtf(var + LN_EPS));
    }
    __syncthreads();

    const int g = lid >> 2;
#pragma unroll
    for (int mt = 0; mt < 2; mt++) {
        const int r0 = wr * 32 + mt * 16 + g;
        const int r1 = r0 + 8;
        const float2 st0 = stat[r0];
        const float2 st1 = stat[r1];
#pragma unroll
        for (int nt = 0; nt < 8; nt++) {
            const int col = wc * 64 + nt * 8 + (lid & 3) * 2;
            const float gm0 = gamma_s[col], gm1 = gamma_s[col + 1];
            const float bt0 = beta_s[col],  bt1 = beta_s[col + 1];
            if (rb + r0 < N_NODES) {
                float2 o;
                o.x = (acc[mt][nt][0] - st0.x) * st0.y * gm0 + bt0;
                o.y = (acc[mt][nt][1] - st0.x) * st0.y * gm1 + bt1;
                *(float2*)&out[(size_t)(rb + r0) * D + col] = o;
            }
            if (rb + r1 < N_NODES) {
                float2 o;
                o.x = (acc[mt][nt][2] - st1.x) * st1.y * gm0 + bt0;
                o.y = (acc[mt][nt][3] - st1.x) * st1.y * gm1 + bt1;
                *(float2*)&out[(size_t)(rb + r1) * D + col] = o;
            }
        }
    }
}

// ---------------------------------------------------------------------------
// Launch
// ---------------------------------------------------------------------------
extern "C" void kernel_launch(void* const* d_in, const int* in_sizes, int n_in,
                              void* d_out, int out_size)
{
    const float* features  = (const float*)d_in[0];
    const int*   neighbors = (const int*)d_in[1];
    const float* weights   = (const float*)d_in[2];
    const float* W         = (const float*)d_in[3];
    const float* bias      = (const float*)d_in[4];
    const float* gamma     = (const float*)d_in[5];
    const float* beta      = (const float*)d_in[6];
    float*       out       = (float*)d_out;

    cudaFuncSetAttribute(fused_gather_gemm_ln,
                         cudaFuncAttributeMaxDynamicSharedMemorySize, SMEM_TOTAL);

    prep_w<<<dim3(8, 8), dim3(32, 8)>>>(W);
    fused_gather_gemm_ln<<<NB, 256, SMEM_TOTAL>>>(
        features, neighbors, weights, bias, gamma, beta, out);
}